// round 14
// baseline (speedup 1.0000x reference)
#include <cuda_runtime.h>
#include <cstdint>

#define NROWS 8192
#define DDIM  8192
#define KIN   1024
#define NT    64

typedef unsigned long long ull;

// ---- packed f32x2 helpers (Blackwell sm_103a) ----
__device__ __forceinline__ ull pack2(float lo, float hi) {
    ull r; asm("mov.b64 %0, {%1, %2};" : "=l"(r) : "f"(lo), "f"(hi)); return r;
}
__device__ __forceinline__ void unpack2(ull v, float& lo, float& hi) {
    asm("mov.b64 {%0, %1}, %2;" : "=f"(lo), "=f"(hi) : "l"(v));
}
__device__ __forceinline__ ull f2add(ull a, ull b) {
    ull r; asm("add.rn.f32x2 %0, %1, %2;" : "=l"(r) : "l"(a), "l"(b)); return r;
}
// a - b == fma(b, -1, a)
__device__ __forceinline__ ull f2sub(ull a, ull b) {
    const ull NEG1 = 0xBF800000BF800000ULL;
    ull r; asm("fma.rn.f32x2 %0, %1, %2, %3;" : "=l"(r) : "l"(b), "l"(NEG1), "l"(a)); return r;
}
__device__ __forceinline__ ull f2mul(ull a, ull b) {
    ull r; asm("mul.rn.f32x2 %0, %1, %2;" : "=l"(r) : "l"(a), "l"(b)); return r;
}

// Storage swizzle: slot(e) = e ^ (((e>>7)&31)<<2)  (perturbs bits 2..6 only;
// preserves quad identity since bits 0..1 untouched)
__device__ __forceinline__ int slot(int e) {
    return e ^ (((e >> 7) & 31) << 2);
}

// Predicated shared ops (guaranteed no BSSY/BSYNC)
__device__ __forceinline__ void sts_pred(uint32_t addr, float v, int pred) {
    asm volatile(
        "{ .reg .pred p; setp.ne.s32 p, %2, 0; @p st.shared.f32 [%0], %1; }"
        :: "r"(addr), "f"(v), "r"(pred) : "memory");
}
__device__ __forceinline__ void sts128_zero_pred(uint32_t addr, unsigned pred) {
    asm volatile(
        "{ .reg .pred p; setp.ne.u32 p, %1, 0;\n\t"
        "@p st.shared.v4.f32 [%0], {0f00000000, 0f00000000, 0f00000000, 0f00000000}; }"
        :: "r"(addr), "r"(pred) : "memory");
}
__device__ __forceinline__ float4 lds128_or_zero(uint32_t addr, unsigned pred) {
    float4 q;
    asm volatile(
        "{ .reg .pred p; setp.ne.u32 p, %5, 0;\n\t"
        "mov.f32 %0, 0f00000000; mov.f32 %1, 0f00000000;\n\t"
        "mov.f32 %2, 0f00000000; mov.f32 %3, 0f00000000;\n\t"
        "@p ld.shared.v4.f32 {%0, %1, %2, %3}, [%4]; }"
        : "=f"(q.x), "=f"(q.y), "=f"(q.z), "=f"(q.w)
        : "r"(addr), "r"(pred));
    return q;
}

__global__ void __launch_bounds__(NT, 6) fwht_kernel(
    const float* __restrict__ u, const int* __restrict__ idx, float* __restrict__ out)
{
    __shared__ float    sm[DDIM];     // 32 KB exchange buffer
    __shared__ unsigned qmask[NT];    // bit c of qmask[t] = e-quad c of thread t has a key
    float4* smv = reinterpret_cast<float4*>(sm);
    uint32_t smbase;
    asm("{ .reg .u64 q; cvta.to.shared.u64 q, %1; cvt.u32.u64 %0, q; }"
        : "=r"(smbase) : "l"(sm));

    const int t   = threadIdx.x;       // 0..63
    const int row = blockIdx.x;
    const float* urow = u + (long)row * KIN;

    // ---- early global loads (16 keys + 16 values + boundary peek) ----
    int4   iv[4];
    float4 uv[4];
    {
        const int4*   idx4 = reinterpret_cast<const int4*>(idx);
        const float4* u4   = reinterpret_cast<const float4*>(urow);
#pragma unroll
        for (int i = 0; i < 4; i++) { iv[i] = idx4[4 * t + i]; uv[i] = u4[4 * t + i]; }
    }
    const int j16 = 16 * t + 16;
    const int prev0  = (t == 0) ? -1 : idx[16 * t - 1];
    const int idnxt  = (j16     < KIN) ? idx[j16]     : -1;
    const int idnxt2 = (j16 + 1 < KIN) ? idx[j16 + 1] : -1;
    const float unxt = (j16     < KIN) ? urow[j16]    : 0.f;

    // ---- (1) clear quad-occupancy bitmap ----
    qmask[t] = 0u;
    __syncthreads();

    int   id[16]; float uu[16];
#pragma unroll
    for (int i = 0; i < 4; i++) {
        id[4*i] = iv[i].x; id[4*i+1] = iv[i].y; id[4*i+2] = iv[i].z; id[4*i+3] = iv[i].w;
        uu[4*i] = uv[i].x; uu[4*i+1] = uv[i].y; uu[4*i+2] = uv[i].z; uu[4*i+3] = uv[i].w;
    }

    // ---- (2) mark each key's e-quad (idempotent atomicOr, spread addresses) ----
#pragma unroll
    for (int p = 0; p < 16; p++)
        atomicOr(&qmask[id[p] >> 7], 1u << ((id[p] >> 2) & 31));
    __syncthreads();

    // ---- (3) zero ONLY marked quads in this thread's segment (~39% of quads) ----
    const int tm = t & 31;
    const int qb = t << 5;               // float4-index base of this thread's 32 quads
    const unsigned mask = qmask[t];
#pragma unroll
    for (int c = 0; c < 32; c++)
        sts128_zero_pred(smbase + ((qb + (c ^ tm)) << 4), mask & (1u << c));
    __syncthreads();

    // ---- (4) scatter: backward run-sum scan + predicated leader stores ----
    {
        float tail = (idnxt == id[15]) ? unxt : 0.f;
        if (idnxt == id[15] && idnxt2 == id[15]) {
            int j = j16 + 1;
            while (j < KIN && idx[j] == id[15]) { tail += urow[j]; j++; }
        }
        float s[16];
        s[15] = uu[15] + tail;
#pragma unroll
        for (int p = 14; p >= 0; p--)
            s[p] = uu[p] + ((id[p + 1] == id[p]) ? s[p + 1] : 0.f);
        int pv = prev0;
#pragma unroll
        for (int p = 0; p < 16; p++) {
            sts_pred(smbase + 4u * (uint32_t)slot(id[p]), s[p], id[p] != pv);
            pv = id[p];
        }
    }
    __syncthreads();

    // ==== Phase 1: thread owns e in [128t, 128t+128); bits 0..6 in registers ====
    // marked quads loaded from smem, unmarked quads are implicit zeros (no traffic)
    {
        ull y[64];
#pragma unroll
        for (int c = 0; c < 32; c++) {
            float4 q = lds128_or_zero(smbase + ((qb + (c ^ tm)) << 4), mask & (1u << c));
            y[2 * c]     = pack2(q.x + q.y, q.x - q.y);   // fold bit 0
            y[2 * c + 1] = pack2(q.z + q.w, q.z - q.w);
        }
        // bits 1..6: 6 packed stages over pair-index p = 0..63
#pragma unroll
        for (int m = 32; m >= 1; m >>= 1) {
#pragma unroll
            for (int j = 0; j < 64; j++) {
                if (!(j & m)) {
                    ull a = y[j], b = y[j | m];
                    y[j]     = f2add(a, b);
                    y[j | m] = f2sub(a, b);
                }
            }
        }
        // write back IN-PLACE, dense (thread-exclusive slots, same addresses)
#pragma unroll
        for (int c = 0; c < 32; c++) {
            float a0, a1, b0, b1;
            unpack2(y[2 * c], a0, a1);
            unpack2(y[2 * c + 1], b0, b1);
            smv[qb + (c ^ tm)] = make_float4(a0, a1, b0, b1);
        }
    }
    __syncthreads();   // P2 reads cross-thread

    // ==== Phase 2: bits 7..12; thread handles tau pair (2t, 2t+1), single pass ====
    // read e = tau + 128m at slot = 128m + (tau ^ ((m&31)<<2)); tau pair adjacent -> LDS.64
    {
        ull z[64];
        const int t2 = 2 * t;
#pragma unroll
        for (int m = 0; m < 64; m++) {
            float2 v = *reinterpret_cast<const float2*>(
                &sm[128 * m + (t2 ^ ((m & 31) << 2))]);
            z[m] = pack2(v.x, v.y);   // packed lanes = (tau0, tau1)
        }
        // 6 packed stages over m (bits 7..12)
#pragma unroll
        for (int mm = 32; mm >= 1; mm >>= 1) {
#pragma unroll
            for (int j = 0; j < 64; j++) {
                if (!(j & mm)) {
                    ull a = z[j], b = z[j | mm];
                    z[j]      = f2add(a, b);
                    z[j | mm] = f2sub(a, b);
                }
            }
        }
        // scale + store: float2 at orow[128m + 2t]  -> STG.64, coalesced
        const float SCALE = 0.011048543456039806f;  // 1/sqrt(8192)
        const ull SC2 = pack2(SCALE, SCALE);
        float2* orow2 = reinterpret_cast<float2*>(out + (long)row * DDIM);
#pragma unroll
        for (int m = 0; m < 64; m++) {
            float lo, hi;
            unpack2(f2mul(z[m], SC2), lo, hi);
            orow2[64 * m + t] = make_float2(lo, hi);
        }
    }
}

extern "C" void kernel_launch(void* const* d_in, const int* in_sizes, int n_in,
                              void* d_out, int out_size)
{
    const float* u   = (const float*)d_in[0];
    const int*   idx = (const int*)d_in[1];
    float*       out = (float*)d_out;
    fwht_kernel<<<NROWS, NT>>>(u, idx, out);
}